// round 5
// baseline (speedup 1.0000x reference)
#include <cuda_runtime.h>
#include <math.h>

#define D_MODEL 1024
#define NHEAD   16
#define DK      64
#define BATCH   2
#define SEQ     2048
#define MROWS   (BATCH * SEQ)
#define NBH     (BATCH * NHEAD)
#define OUT_ELEMS ((size_t)MROWS * D_MODEL)

// Scratch (no cudaMalloc allowed)
__device__ float g_Q[MROWS * D_MODEL];
__device__ float g_K[MROWS * D_MODEL];
__device__ float g_V[MROWS * D_MODEL];
__device__ float g_ctx[MROWS * D_MODEL];
__device__ float g_s[NBH * SEQ];

// ---------------------------------------------------------------------------
__device__ __forceinline__ unsigned f2tf(float f) {
    unsigned u;
    asm("cvt.rna.tf32.f32 %0, %1;" : "=r"(u) : "f"(f));
    return u;
}

__device__ __forceinline__ uint2 tf_pair(float f) {
    unsigned h = f2tf(f);
    return make_uint2(h, f2tf(f - __uint_as_float(h)));
}

__device__ __forceinline__ void mma_tf32(float* c, const unsigned* a, const unsigned* b) {
    asm volatile(
        "mma.sync.aligned.m16n8k8.row.col.f32.tf32.tf32.f32 "
        "{%0,%1,%2,%3},{%4,%5,%6,%7},{%8,%9},{%0,%1,%2,%3};"
        : "+f"(c[0]), "+f"(c[1]), "+f"(c[2]), "+f"(c[3])
        : "r"(a[0]), "r"(a[1]), "r"(a[2]), "r"(a[3]), "r"(b[0]), "r"(b[1]));
}

// Warp tile 64(m) x 32(n) over one BK=16 stage, interleaved hi/lo smem.
// A layout: 16 k-rows of AS2 words; element m at word m*2 ({hi,lo}).
// B layout: 16 k-rows of BS2 words; element n at word n*2.
template<int AS2, int BS2>
__device__ __forceinline__ void warp_mma16i(
    float (*acc)[4][4], const unsigned* A, const unsigned* B,
    int m0base, int n0base, int lane)
{
    int r = lane >> 2, t = lane & 3;
    #pragma unroll
    for (int ks = 0; ks < 16; ks += 8) {
        const unsigned* Ar0 = A + (ks + t) * AS2;
        const unsigned* Ar1 = A + (ks + t + 4) * AS2;
        const unsigned* Br0 = B + (ks + t) * BS2;
        const unsigned* Br1 = B + (ks + t + 4) * BS2;
        uint2 bf0[4], bf1[4];
        #pragma unroll
        for (int ni = 0; ni < 4; ni++) {
            int n0 = (n0base + ni * 8 + r) * 2;
            bf0[ni] = *(const uint2*)(Br0 + n0);
            bf1[ni] = *(const uint2*)(Br1 + n0);
        }
        #pragma unroll
        for (int mi = 0; mi < 4; mi++) {
            int m0 = (m0base + mi * 16 + r) * 2;
            uint2 a00 = *(const uint2*)(Ar0 + m0);
            uint2 a01 = *(const uint2*)(Ar0 + m0 + 16);
            uint2 a10 = *(const uint2*)(Ar1 + m0);
            uint2 a11 = *(const uint2*)(Ar1 + m0 + 16);
            unsigned ah[4] = {a00.x, a01.x, a10.x, a11.x};
            unsigned al[4] = {a00.y, a01.y, a10.y, a11.y};
            #pragma unroll
            for (int ni = 0; ni < 4; ni++) {
                unsigned bh[2] = {bf0[ni].x, bf1[ni].x};
                unsigned bl[2] = {bf0[ni].y, bf1[ni].y};
                mma_tf32(acc[mi][ni], ah, bh);
                mma_tf32(acc[mi][ni], ah, bl);
                mma_tf32(acc[mi][ni], al, bh);
            }
        }
    }
}

// ---------------------------------------------------------------------------
// Projection GEMM: Y = X @ W + b.  BM=128, BN=128, BK=16, double-buffered.
// smem units: per buffer [A 16x264 | B 16x264] = 8448; 2 buffers.
// ---------------------------------------------------------------------------
#define PROJ_SMEM_BYTES (2 * 8448 * 4)

__global__ __launch_bounds__(256, 2) void gemm_bias_tc(
    const float* __restrict__ X, const float* __restrict__ W,
    const float* __restrict__ bias, float* __restrict__ Y)
{
    extern __shared__ unsigned sm[];

    int tid = threadIdx.x, lane = tid & 31, warp = tid >> 5;
    int warpM = warp >> 2, warpN = warp & 3;
    int rowBase = blockIdx.y * 128;
    int colBase = blockIdx.x * 128;

    const float* Xb = X + (size_t)rowBase * D_MODEL;
    const float* Wb = W + colBase;

    float acc[4][4][4] = {};
    float4 av[2], bv[2];

    #pragma unroll
    for (int i = 0; i < 2; i++) {
        int e = tid + i * 256;
        av[i] = *(const float4*)(Xb + (size_t)(e >> 2) * D_MODEL + (e & 3) * 4);
        bv[i] = *(const float4*)(Wb + (size_t)(e >> 5) * D_MODEL + (e & 31) * 4);
    }

    auto store_stage = [&](int b) {
        unsigned* Ab = sm + b * 8448;
        unsigned* Bb = Ab + 4224;
        #pragma unroll
        for (int i = 0; i < 2; i++) {
            int e = tid + i * 256;
            {
                int m = e >> 2, k = (e & 3) * 4;
                float f[4] = {av[i].x, av[i].y, av[i].z, av[i].w};
                #pragma unroll
                for (int j = 0; j < 4; j++)
                    *(uint2*)(Ab + (k + j) * 264 + m * 2) = tf_pair(f[j]);
            }
            {
                int k = e >> 5, n = (e & 31) * 4;
                uint2 p0 = tf_pair(bv[i].x), p1 = tf_pair(bv[i].y);
                uint2 p2 = tf_pair(bv[i].z), p3 = tf_pair(bv[i].w);
                unsigned* dst = Bb + k * 264 + n * 2;
                *(uint4*)(dst)     = make_uint4(p0.x, p0.y, p1.x, p1.y);
                *(uint4*)(dst + 4) = make_uint4(p2.x, p2.y, p3.x, p3.y);
            }
        }
    };

    store_stage(0);
    __syncthreads();

    const int NST = D_MODEL / 16;   // 64
    for (int s = 0; s < NST; s++) {
        int cur = s & 1;
        if (s + 1 < NST) {
            const float* Xn = Xb + (s + 1) * 16;
            const float* Wn = Wb + (size_t)((s + 1) * 16) * D_MODEL;
            #pragma unroll
            for (int i = 0; i < 2; i++) {
                int e = tid + i * 256;
                av[i] = *(const float4*)(Xn + (size_t)(e >> 2) * D_MODEL + (e & 3) * 4);
                bv[i] = *(const float4*)(Wn + (size_t)(e >> 5) * D_MODEL + (e & 31) * 4);
            }
        }
        warp_mma16i<264, 264>(acc, sm + cur * 8448, sm + cur * 8448 + 4224,
                              warpM * 64, warpN * 32, lane);
        if (s + 1 < NST) store_stage(cur ^ 1);
        __syncthreads();
    }

    int r = lane >> 2, t = lane & 3;
    #pragma unroll
    for (int mi = 0; mi < 4; mi++) {
        int row0 = rowBase + warpM * 64 + mi * 16 + r;
        #pragma unroll
        for (int ni = 0; ni < 4; ni++) {
            int col = colBase + warpN * 32 + ni * 8 + t * 2;
            float2 b2 = *(const float2*)&bias[col];
            float2 v0 = {acc[mi][ni][0] + b2.x, acc[mi][ni][1] + b2.y};
            float2 v1 = {acc[mi][ni][2] + b2.x, acc[mi][ni][3] + b2.y};
            *(float2*)&Y[(size_t)row0 * D_MODEL + col] = v0;
            *(float2*)&Y[(size_t)(row0 + 8) * D_MODEL + col] = v1;
        }
    }
}

// ---------------------------------------------------------------------------
// scores: writes e = exp(score) (no max subtraction; scores bounded) plus
// per-row sum-of-exp to g_s. Q tile hoisted; K tiles double-buffered.
// smem units: Q 64x264=16896 | Kbufs 2*(16x264)=8448 | RedS 512
// ---------------------------------------------------------------------------
#define SC_K_OFF    16896
#define SC_RS_OFF   (16896 + 8448)
#define SC_SMEM_BYTES ((SC_RS_OFF + 512) * 4)

__global__ __launch_bounds__(256, 2) void scores_tc(
    const float* __restrict__ Q, const float* __restrict__ Kmat,
    float* __restrict__ attn)
{
    extern __shared__ unsigned sm[];
    unsigned* Qs = sm;
    unsigned* kb = sm + SC_K_OFF;
    float (*RedS)[128] = (float(*)[128])(sm + SC_RS_OFF);

    int tid = threadIdx.x, lane = tid & 31, warp = tid >> 5;
    int warpM = warp >> 2, warpN = warp & 3;
    int qBase = blockIdx.x * 128;
    int bh = blockIdx.y, b = bh >> 4, h = bh & 15;
    int r = lane >> 2, t = lane & 3;

    const float* Qb  = Q    + ((size_t)(b * SEQ + qBase)) * D_MODEL + h * DK;
    const float* Kb0 = Kmat + ((size_t)(b * SEQ))         * D_MODEL + h * DK;

    // Hoist full 128x64 Q tile into smem (64 k-rows x 128 m, interleaved).
    #pragma unroll
    for (int i = 0; i < 8; i++) {
        int e = tid + i * 256;
        int m = e >> 4, k = (e & 15) * 4;
        float4 v = *(const float4*)(Qb + (size_t)m * D_MODEL + k);
        float f[4] = {v.x, v.y, v.z, v.w};
        #pragma unroll
        for (int j = 0; j < 4; j++)
            *(uint2*)(Qs + (k + j) * 264 + m * 2) = tf_pair(f[j]);
    }

    float4 bv[2];
    #pragma unroll
    for (int i = 0; i < 2; i++) {
        int e = tid + i * 256;
        bv[i] = *(const float4*)(Kb0 + (size_t)(e >> 2) * D_MODEL + (e & 3) * 4);
    }

    auto kstore = [&](int buf) {
        unsigned* Bb = kb + buf * 4224;
        #pragma unroll
        for (int i = 0; i < 2; i++) {
            int e = tid + i * 256;
            int n = e >> 2, k = (e & 3) * 4;
            float f[4] = {bv[i].x, bv[i].y, bv[i].z, bv[i].w};
            #pragma unroll
            for (int j = 0; j < 4; j++)
                *(uint2*)(Bb + (k + j) * 264 + n * 2) = tf_pair(f[j]);
        }
    };

    kstore(0);
    __syncthreads();

    float rs[8];
    #pragma unroll
    for (int j = 0; j < 8; j++) rs[j] = 0.0f;

    const float scale = 0.125f;
    const int NSTAGE = 64;   // 16 s-tiles x 4 k-chunks

    for (int st = 0; st < 16; st++) {
        int sBase = st * 128;
        float acc[4][4][4] = {};

        #pragma unroll
        for (int kk = 0; kk < 4; kk++) {
            int stage = st * 4 + kk;
            int cur = stage & 1;
            if (stage + 1 < NSTAGE) {
                int nst = (stage + 1) >> 2, nkk = (stage + 1) & 3;
                const float* Kb = Kb0 + (size_t)(nst * 128) * D_MODEL + nkk * 16;
                #pragma unroll
                for (int i = 0; i < 2; i++) {
                    int e = tid + i * 256;
                    bv[i] = *(const float4*)(Kb + (size_t)(e >> 2) * D_MODEL + (e & 3) * 4);
                }
            }
            warp_mma16i<264, 264>(acc, Qs + kk * 16 * 264, kb + cur * 4224,
                                  warpM * 64, warpN * 32, lane);
            if (stage + 1 < NSTAGE) kstore(cur ^ 1);
            __syncthreads();
        }

        // Epilogue: e = exp(score), write, accumulate row sums.
        #pragma unroll
        for (int mi = 0; mi < 4; mi++) {
            #pragma unroll
            for (int hh = 0; hh < 2; hh++) {
                int row = qBase + warpM * 64 + mi * 16 + hh * 8 + r;
                size_t rowOff = ((size_t)bh * SEQ + row) * SEQ;
                int j = mi * 2 + hh;
                float add = 0.0f;
                #pragma unroll
                for (int ni = 0; ni < 4; ni++) {
                    float e0 = __expf(acc[mi][ni][hh * 2 + 0] * scale);
                    float e1 = __expf(acc[mi][ni][hh * 2 + 1] * scale);
                    int col = sBase + warpN * 32 + ni * 8 + t * 2;
                    *(float2*)&attn[rowOff + col] = make_float2(e0, e1);
                    add += e0 + e1;
                }
                rs[j] += add;
            }
        }
    }

    // Reduce sums across the 4 t-lanes sharing each row.
    #pragma unroll
    for (int off = 1; off <= 2; off <<= 1)
        #pragma unroll
        for (int j = 0; j < 8; j++)
            rs[j] += __shfl_xor_sync(0xFFFFFFFFu, rs[j], off);
    if (t == 0) {
        #pragma unroll
        for (int mi = 0; mi < 4; mi++)
            #pragma unroll
            for (int hh = 0; hh < 2; hh++) {
                int row = warpM * 64 + mi * 16 + hh * 8 + r;
                RedS[warpN][row] = rs[mi * 2 + hh];
            }
    }
    __syncthreads();
    if (tid < 128) {
        float s = RedS[0][tid] + RedS[1][tid] + RedS[2][tid] + RedS[3][tid];
        g_s[(size_t)bh * SEQ + qBase + tid] = s;
    }
}

// ---------------------------------------------------------------------------
// ctx: reads e, normalizes p = e / s (writes normalized attn), ctx = P @ V.
// BM=256(q), BN=64(dk), BK=16(s), double-buffered. 8 warps (4m x 2n).
// smem units per buffer: A 16x520=8320 | B 16x136=2176 = 10496; 2 bufs;
// smI 256 at +20992.
// ---------------------------------------------------------------------------
#define CTX_SMI_OFF 20992
#define CTX_SMEM_BYTES ((CTX_SMI_OFF + 256) * 4)

__global__ __launch_bounds__(256, 2) void ctx_tc(
    float* __restrict__ attn, const float* __restrict__ V,
    float* __restrict__ ctx)
{
    extern __shared__ unsigned sm[];
    float* smI = (float*)(sm + CTX_SMI_OFF);

    int tid = threadIdx.x, lane = tid & 31, warp = tid >> 5;
    int warpM = warp >> 1, warpN = warp & 1;
    int qBase = blockIdx.x * 256;
    int bh = blockIdx.y, b = bh >> 4, h = bh & 15;
    int r = lane >> 2, t = lane & 3;

    smI[tid] = 1.0f / g_s[(size_t)bh * SEQ + qBase + tid];

    float* Ab = attn + ((size_t)bh * SEQ + qBase) * SEQ;
    const float* Vb = V + ((size_t)(b * SEQ)) * D_MODEL + h * DK;

    float acc[4][4][4] = {};
    float4 av[4], bvv;

    #pragma unroll
    for (int i = 0; i < 4; i++) {
        int e = tid + i * 256;
        av[i] = *(const float4*)(Ab + (size_t)(e >> 2) * SEQ + (e & 3) * 4);
    }
    bvv = *(const float4*)(Vb + (size_t)(tid >> 4) * D_MODEL + (tid & 15) * 4);
    __syncthreads();   // smI visible

    auto store_stage = [&](int buf, int kpos) {
        unsigned* As = sm + buf * 10496;
        unsigned* Bs = As + 8320;
        #pragma unroll
        for (int i = 0; i < 4; i++) {
            int e = tid + i * 256;
            int m = e >> 2, k = (e & 3) * 4;
            float mI = smI[m];
            float p0 = av[i].x * mI, p1 = av[i].y * mI;
            float p2 = av[i].z * mI, p3 = av[i].w * mI;
            *(float4*)(Ab + (size_t)m * SEQ + kpos * 16 + k) = make_float4(p0, p1, p2, p3);
            *(uint2*)(As + (k + 0) * 520 + m * 2) = tf_pair(p0);
            *(uint2*)(As + (k + 1) * 520 + m * 2) = tf_pair(p1);
            *(uint2*)(As + (k + 2) * 520 + m * 2) = tf_pair(p2);
            *(uint2*)(As + (k + 3) * 520 + m * 2) = tf_pair(p3);
        }
        {
            int k = tid >> 4, n = (tid & 15) * 4;
            uint2 p0 = tf_pair(bvv.x), p1 = tf_pair(bvv.y);
            uint2 p2 = tf_pair(bvv.z), p3 = tf_pair(bvv.w);
            unsigned* dst = Bs + k * 136 + n * 2;
            *(uint4*)(dst)     = make_uint4(p0.x, p0.y, p1.x, p1.y);
            *(uint4*)(dst + 4) = make_uint4(p2.x, p2.y, p3.x, p3.y);
        }
    };

    store_stage(0, 0);
    __syncthreads();

    const int NST = SEQ / 16;   // 128
    for (int s = 0; s < NST; s++) {
        int cur = s & 1;
        if (s + 1 < NST) {
            int k0 = (s + 1) * 16;
            #pragma unroll
            for (int i = 0; i < 4; i++) {
                int e = tid + i * 256;
                av[i] = *(const float4*)(Ab + (size_t)(e >> 2) * SEQ + k0 + (e & 3) * 4);
            }
            bvv = *(const float4*)(Vb + (size_t)(k0 + (tid >> 4)) * D_MODEL + (tid & 15) * 4);
        }
        warp_mma16i<520, 136>(acc, sm + cur * 10496, sm + cur * 10496 + 8320,
                              warpM * 64, warpN * 32, lane);
        if (s + 1 < NST) store_stage(cur ^ 1, s + 1);
        __syncthreads();
    }

    #pragma unroll
    for (int mi = 0; mi < 4; mi++) {
        int q0 = qBase + warpM * 64 + mi * 16 + r;
        #pragma unroll
        for (int ni = 0; ni < 4; ni++) {
            int col = warpN * 32 + ni * 8 + t * 2;
            float2 v0 = {acc[mi][ni][0], acc[mi][ni][1]};
            float2 v1 = {acc[mi][ni][2], acc[mi][ni][3]};
            *(float2*)&ctx[((size_t)(b * SEQ + q0)) * D_MODEL + h * DK + col] = v0;
            *(float2*)&ctx[((size_t)(b * SEQ + q0 + 8)) * D_MODEL + h * DK + col] = v1;
        }
    }
}

// ---------------------------------------------------------------------------
extern "C" void kernel_launch(void* const* d_in, const int* in_sizes, int n_in,
                              void* d_out, int out_size)
{
    const float* query = (const float*)d_in[0];
    const float* key   = (const float*)d_in[1];
    const float* value = (const float*)d_in[2];
    const float* Wq = (const float*)d_in[3];
    const float* bq = (const float*)d_in[4];
    const float* Wk = (const float*)d_in[5];
    const float* bk = (const float*)d_in[6];
    const float* Wv = (const float*)d_in[7];
    const float* bv = (const float*)d_in[8];
    const float* Wo = (const float*)d_in[9];
    const float* bo = (const float*)d_in[10];

    float* out  = (float*)d_out;
    float* attn = (float*)d_out + OUT_ELEMS;

    float* Qp; cudaGetSymbolAddress((void**)&Qp, g_Q);
    float* Kp; cudaGetSymbolAddress((void**)&Kp, g_K);
    float* Vp; cudaGetSymbolAddress((void**)&Vp, g_V);
    float* Cp; cudaGetSymbolAddress((void**)&Cp, g_ctx);

    static int configured = 0;
    if (!configured) {
        cudaFuncSetAttribute(gemm_bias_tc, cudaFuncAttributeMaxDynamicSharedMemorySize,
                             PROJ_SMEM_BYTES);
        cudaFuncSetAttribute(scores_tc, cudaFuncAttributeMaxDynamicSharedMemorySize,
                             SC_SMEM_BYTES);
        cudaFuncSetAttribute(ctx_tc, cudaFuncAttributeMaxDynamicSharedMemorySize,
                             CTX_SMEM_BYTES);
        configured = 1;
    }

    dim3 gProj(D_MODEL / 128, MROWS / 128);   // (8, 32)
    dim3 gScores(SEQ / 128, NBH);             // (16, 32)
    dim3 gCtx(SEQ / 256, NBH);                // (8, 32)

    gemm_bias_tc<<<gProj, 256, PROJ_SMEM_BYTES>>>(query, Wq, bq, Qp);
    gemm_bias_tc<<<gProj, 256, PROJ_SMEM_BYTES>>>(key,   Wk, bk, Kp);
    gemm_bias_tc<<<gProj, 256, PROJ_SMEM_BYTES>>>(value, Wv, bv, Vp);

    scores_tc<<<gScores, 256, SC_SMEM_BYTES>>>(Qp, Kp, attn);
    ctx_tc<<<gCtx, 256, CTX_SMEM_BYTES>>>(attn, Vp, Cp);

    gemm_bias_tc<<<gProj, 256, PROJ_SMEM_BYTES>>>(Cp, Wo, bo, out);
}

// round 6
// speedup vs baseline: 1.5333x; 1.5333x over previous
#include <cuda_runtime.h>
#include <cuda_bf16.h>
#include <math.h>

#define D_MODEL 1024
#define NHEAD   16
#define DK      64
#define BATCH   2
#define SEQ     2048
#define MROWS   (BATCH * SEQ)
#define NBH     (BATCH * NHEAD)
#define OUT_ELEMS ((size_t)MROWS * D_MODEL)

typedef __nv_bfloat16 bf16;

// Scratch (no cudaMalloc allowed)
__device__ float g_Q[MROWS * D_MODEL];
__device__ float g_K[MROWS * D_MODEL];
__device__ float g_V[MROWS * D_MODEL];
__device__ float g_ctx[MROWS * D_MODEL];
__device__ float g_s[NBH * SEQ];

// ---------------------------------------------------------------------------
__device__ __forceinline__ unsigned smaddr(const void* p) {
    return (unsigned)__cvta_generic_to_shared(p);
}

// Split 4 consecutive fp32 into bf16 hi + bf16 lo arrays (4 halves each).
__device__ __forceinline__ void splitstore4(float4 v, bf16* hb, bf16* lb) {
    float f[4] = {v.x, v.y, v.z, v.w};
    unsigned h[2], l[2];
    #pragma unroll
    for (int i = 0; i < 2; i++) {
        bf16 a = __float2bfloat16(f[2*i]);
        bf16 b = __float2bfloat16(f[2*i+1]);
        h[i] = ((unsigned)__bfloat16_as_ushort(b) << 16) | __bfloat16_as_ushort(a);
        bf16 ra = __float2bfloat16(f[2*i]   - __bfloat162float(a));
        bf16 rb = __float2bfloat16(f[2*i+1] - __bfloat162float(b));
        l[i] = ((unsigned)__bfloat16_as_ushort(rb) << 16) | __bfloat16_as_ushort(ra);
    }
    *(uint2*)hb = make_uint2(h[0], h[1]);
    *(uint2*)lb = make_uint2(l[0], l[1]);
}

__device__ __forceinline__ void mma_bf16(float* c, const unsigned* a, const unsigned* b) {
    asm volatile(
        "mma.sync.aligned.m16n8k16.row.col.f32.bf16.bf16.f32 "
        "{%0,%1,%2,%3},{%4,%5,%6,%7},{%8,%9},{%0,%1,%2,%3};"
        : "+f"(c[0]), "+f"(c[1]), "+f"(c[2]), "+f"(c[3])
        : "r"(a[0]), "r"(a[1]), "r"(a[2]), "r"(a[3]), "r"(b[0]), "r"(b[1]));
}

__device__ __forceinline__ void ldsm4(unsigned& r0, unsigned& r1, unsigned& r2,
                                      unsigned& r3, unsigned a) {
    asm volatile("ldmatrix.sync.aligned.m8n8.x4.shared.b16 {%0,%1,%2,%3}, [%4];"
        : "=r"(r0), "=r"(r1), "=r"(r2), "=r"(r3) : "r"(a));
}
__device__ __forceinline__ void ldsm4t(unsigned& r0, unsigned& r1, unsigned& r2,
                                       unsigned& r3, unsigned a) {
    asm volatile("ldmatrix.sync.aligned.m8n8.x4.trans.shared.b16 {%0,%1,%2,%3}, [%4];"
        : "=r"(r0), "=r"(r1), "=r"(r2), "=r"(r3) : "r"(a));
}

// Warp tile 64(m) x 32(n), one k16 slab, 3-term bf16. A: [m][k] rows (SA halves).
// B: BT=false -> [n][k] rows (SB halves); BT=true -> [k][n] rows.
template<int SA, int SB, bool BT>
__device__ __forceinline__ void warp_mma_k16(
    float (*acc)[4][4],
    const bf16* Ah, const bf16* Al, const bf16* Bh, const bf16* Bl,
    int m0base, int n0base, int k0a, int k0b, int lane)
{
    int g = lane >> 3, r = lane & 7;
    unsigned ah[4][4], al[4][4], bh[4][2], bl[4][2];

    int arow = (g & 1) * 8 + r, acol = k0a + (g >> 1) * 8;
    #pragma unroll
    for (int mi = 0; mi < 4; mi++) {
        int row = m0base + mi * 16 + arow;
        ldsm4(ah[mi][0], ah[mi][1], ah[mi][2], ah[mi][3], smaddr(Ah + row * SA + acol));
        ldsm4(al[mi][0], al[mi][1], al[mi][2], al[mi][3], smaddr(Al + row * SA + acol));
    }
    #pragma unroll
    for (int nj = 0; nj < 2; nj++) {
        int n0 = n0base + nj * 16;
        unsigned q0, q1, q2, q3;
        if (BT) {
            int row = k0b + (g & 1) * 8 + r;
            int col = n0 + (g >> 1) * 8;
            ldsm4t(q0, q1, q2, q3, smaddr(Bh + row * SB + col));
            bh[nj*2][0] = q0; bh[nj*2][1] = q1; bh[nj*2+1][0] = q2; bh[nj*2+1][1] = q3;
            ldsm4t(q0, q1, q2, q3, smaddr(Bl + row * SB + col));
            bl[nj*2][0] = q0; bl[nj*2][1] = q1; bl[nj*2+1][0] = q2; bl[nj*2+1][1] = q3;
        } else {
            int row = n0 + (g >> 1) * 8 + r;
            int col = k0b + (g & 1) * 8;
            ldsm4(q0, q1, q2, q3, smaddr(Bh + row * SB + col));
            bh[nj*2][0] = q0; bh[nj*2][1] = q1; bh[nj*2+1][0] = q2; bh[nj*2+1][1] = q3;
            ldsm4(q0, q1, q2, q3, smaddr(Bl + row * SB + col));
            bl[nj*2][0] = q0; bl[nj*2][1] = q1; bl[nj*2+1][0] = q2; bl[nj*2+1][1] = q3;
        }
    }
    #pragma unroll
    for (int mi = 0; mi < 4; mi++)
        #pragma unroll
        for (int ni = 0; ni < 4; ni++) {
            mma_bf16(acc[mi][ni], ah[mi], bh[ni]);
            mma_bf16(acc[mi][ni], ah[mi], bl[ni]);
            mma_bf16(acc[mi][ni], al[mi], bh[ni]);
        }
}

// ---------------------------------------------------------------------------
// Projection GEMM: Y = X @ W + b. BM=128, BN=128, BK=16, double-buffered.
// Stage (halves): Ah[128][24]=3072 | Al 3072 | Bh[16][136]=2176 | Bl 2176 = 10496.
// ---------------------------------------------------------------------------
#define PJ_STAGE 10496
#define PJ_SMEM_BYTES (2 * PJ_STAGE * 2)

__global__ __launch_bounds__(256) void gemm_bias_tc(
    const float* __restrict__ X, const float* __restrict__ W,
    const float* __restrict__ bias, float* __restrict__ Y)
{
    extern __shared__ bf16 smb[];

    int tid = threadIdx.x, lane = tid & 31, warp = tid >> 5;
    int warpM = warp >> 2, warpN = warp & 3;
    int rowBase = blockIdx.y * 128;
    int colBase = blockIdx.x * 128;

    const float* Xb = X + (size_t)rowBase * D_MODEL;
    const float* Wb = W + colBase;

    float acc[4][4][4] = {};
    float4 av[2], bv[2];

    #pragma unroll
    for (int i = 0; i < 2; i++) {
        int e = tid + i * 256;
        av[i] = *(const float4*)(Xb + (size_t)(e >> 2) * D_MODEL + (e & 3) * 4);
        bv[i] = *(const float4*)(Wb + (size_t)(e >> 5) * D_MODEL + (e & 31) * 4);
    }

    auto store_stage = [&](int buf) {
        bf16* Ah = smb + buf * PJ_STAGE;
        bf16* Al = Ah + 3072;
        bf16* Bh = Ah + 6144;
        bf16* Bl = Ah + 8320;
        #pragma unroll
        for (int i = 0; i < 2; i++) {
            int e = tid + i * 256;
            { int m = e >> 2, k = (e & 3) * 4;
              splitstore4(av[i], Ah + m * 24 + k, Al + m * 24 + k); }
            { int k = e >> 5, n = (e & 31) * 4;
              splitstore4(bv[i], Bh + k * 136 + n, Bl + k * 136 + n); }
        }
    };

    store_stage(0);
    __syncthreads();

    const int NST = D_MODEL / 16;   // 64
    for (int s = 0; s < NST; s++) {
        int cur = s & 1;
        if (s + 1 < NST) {
            const float* Xn = Xb + (s + 1) * 16;
            const float* Wn = Wb + (size_t)((s + 1) * 16) * D_MODEL;
            #pragma unroll
            for (int i = 0; i < 2; i++) {
                int e = tid + i * 256;
                av[i] = *(const float4*)(Xn + (size_t)(e >> 2) * D_MODEL + (e & 3) * 4);
                bv[i] = *(const float4*)(Wn + (size_t)(e >> 5) * D_MODEL + (e & 31) * 4);
            }
        }
        bf16* base = smb + cur * PJ_STAGE;
        warp_mma_k16<24, 136, true>(acc, base, base + 3072, base + 6144, base + 8320,
                                    warpM * 64, warpN * 32, 0, 0, lane);
        if (s + 1 < NST) store_stage(cur ^ 1);
        __syncthreads();
    }

    int r = lane >> 2, t = lane & 3;
    #pragma unroll
    for (int mi = 0; mi < 4; mi++) {
        int row0 = rowBase + warpM * 64 + mi * 16 + r;
        #pragma unroll
        for (int ni = 0; ni < 4; ni++) {
            int col = colBase + warpN * 32 + ni * 8 + t * 2;
            float2 b2 = *(const float2*)&bias[col];
            float2 v0 = {acc[mi][ni][0] + b2.x, acc[mi][ni][1] + b2.y};
            float2 v1 = {acc[mi][ni][2] + b2.x, acc[mi][ni][3] + b2.y};
            *(float2*)&Y[(size_t)row0 * D_MODEL + col] = v0;
            *(float2*)&Y[(size_t)(row0 + 8) * D_MODEL + col] = v1;
        }
    }
}

// ---------------------------------------------------------------------------
// scores: e = exp(score) (no max subtraction; scores bounded) + row sums.
// Q tile [128q][64d] hoisted (stride 72); K chunks [128s][16d] (stride 24),
// double-buffered. Halves: Qh 9216 | Ql 9216 | 2 x (Kh 3072 | Kl 3072) | RedS.
// ---------------------------------------------------------------------------
#define SC_QL 9216
#define SC_KB 18432
#define SC_RS_BYTES 61440
#define SC_SMEM_BYTES (SC_RS_BYTES + 2048)

__global__ __launch_bounds__(256) void scores_tc(
    const float* __restrict__ Q, const float* __restrict__ Kmat,
    float* __restrict__ attn)
{
    extern __shared__ bf16 smb[];
    bf16* Qh = smb;
    bf16* Ql = smb + SC_QL;
    float (*RedS)[128] = (float(*)[128])((char*)smb + SC_RS_BYTES);

    int tid = threadIdx.x, lane = tid & 31, warp = tid >> 5;
    int warpM = warp >> 2, warpN = warp & 3;
    int qBase = blockIdx.x * 128;
    int bh = blockIdx.y, b = bh >> 4, h = bh & 15;
    int r = lane >> 2, t = lane & 3;

    const float* Qb  = Q    + ((size_t)(b * SEQ + qBase)) * D_MODEL + h * DK;
    const float* Kb0 = Kmat + ((size_t)(b * SEQ))         * D_MODEL + h * DK;

    // Hoist full 128x64 Q tile.
    #pragma unroll
    for (int i = 0; i < 8; i++) {
        int e = tid + i * 256;
        int m = e >> 4, k = (e & 15) * 4;
        float4 v = *(const float4*)(Qb + (size_t)m * D_MODEL + k);
        splitstore4(v, Qh + m * 72 + k, Ql + m * 72 + k);
    }

    float4 bv[2];
    #pragma unroll
    for (int i = 0; i < 2; i++) {
        int e = tid + i * 256;
        bv[i] = *(const float4*)(Kb0 + (size_t)(e >> 2) * D_MODEL + (e & 3) * 4);
    }

    auto kstore = [&](int buf) {
        bf16* Kh = smb + SC_KB + buf * 6144;
        bf16* Kl = Kh + 3072;
        #pragma unroll
        for (int i = 0; i < 2; i++) {
            int e = tid + i * 256;
            int n = e >> 2, k = (e & 3) * 4;
            splitstore4(bv[i], Kh + n * 24 + k, Kl + n * 24 + k);
        }
    };

    kstore(0);
    __syncthreads();

    float rs[8];
    #pragma unroll
    for (int j = 0; j < 8; j++) rs[j] = 0.0f;

    const float scale = 0.125f;
    const int NSTAGE = 64;   // 16 s-tiles x 4 d-chunks

    for (int st = 0; st < 16; st++) {
        int sBase = st * 128;
        float acc[4][4][4] = {};

        #pragma unroll
        for (int kk = 0; kk < 4; kk++) {
            int stage = st * 4 + kk;
            int cur = stage & 1;
            if (stage + 1 < NSTAGE) {
                int nst = (stage + 1) >> 2, nkk = (stage + 1) & 3;
                const float* Kb = Kb0 + (size_t)(nst * 128) * D_MODEL + nkk * 16;
                #pragma unroll
                for (int i = 0; i < 2; i++) {
                    int e = tid + i * 256;
                    bv[i] = *(const float4*)(Kb + (size_t)(e >> 2) * D_MODEL + (e & 3) * 4);
                }
            }
            bf16* Kh = smb + SC_KB + cur * 6144;
            warp_mma_k16<72, 24, false>(acc, Qh, Ql, Kh, Kh + 3072,
                                        warpM * 64, warpN * 32, kk * 16, 0, lane);
            if (stage + 1 < NSTAGE) kstore(cur ^ 1);
            __syncthreads();
        }

        // Epilogue: e = exp(score), write, accumulate row sums.
        #pragma unroll
        for (int mi = 0; mi < 4; mi++) {
            #pragma unroll
            for (int hh = 0; hh < 2; hh++) {
                int row = qBase + warpM * 64 + mi * 16 + hh * 8 + r;
                size_t rowOff = ((size_t)bh * SEQ + row) * SEQ;
                int j = mi * 2 + hh;
                float add = 0.0f;
                #pragma unroll
                for (int ni = 0; ni < 4; ni++) {
                    float e0 = __expf(acc[mi][ni][hh * 2 + 0] * scale);
                    float e1 = __expf(acc[mi][ni][hh * 2 + 1] * scale);
                    int col = sBase + warpN * 32 + ni * 8 + t * 2;
                    *(float2*)&attn[rowOff + col] = make_float2(e0, e1);
                    add += e0 + e1;
                }
                rs[j] += add;
            }
        }
    }

    #pragma unroll
    for (int off = 1; off <= 2; off <<= 1)
        #pragma unroll
        for (int j = 0; j < 8; j++)
            rs[j] += __shfl_xor_sync(0xFFFFFFFFu, rs[j], off);
    if (t == 0) {
        #pragma unroll
        for (int mi = 0; mi < 4; mi++)
            #pragma unroll
            for (int hh = 0; hh < 2; hh++) {
                int row = warpM * 64 + mi * 16 + hh * 8 + r;
                RedS[warpN][row] = rs[mi * 2 + hh];
            }
    }
    __syncthreads();
    if (tid < 128) {
        float s = RedS[0][tid] + RedS[1][tid] + RedS[2][tid] + RedS[3][tid];
        g_s[(size_t)bh * SEQ + qBase + tid] = s;
    }
}

// ---------------------------------------------------------------------------
// ctx: p = e / s (writes normalized attn), ctx = P @ V.
// BM=256(q), BN=64(dk), BK=16(s), double-buffered.
// Stage (halves): Ah[256][24]=6144 | Al 6144 | Bh[16][72]=1152 | Bl 1152 = 14592.
// ---------------------------------------------------------------------------
#define CT_STAGE 14592
#define CT_SMI_BYTES 58368
#define CT_SMEM_BYTES (CT_SMI_BYTES + 1024)

__global__ __launch_bounds__(256) void ctx_tc(
    float* __restrict__ attn, const float* __restrict__ V,
    float* __restrict__ ctx)
{
    extern __shared__ bf16 smb[];
    float* smI = (float*)((char*)smb + CT_SMI_BYTES);

    int tid = threadIdx.x, lane = tid & 31, warp = tid >> 5;
    int warpM = warp >> 1, warpN = warp & 1;
    int qBase = blockIdx.x * 256;
    int bh = blockIdx.y, b = bh >> 4, h = bh & 15;
    int r = lane >> 2, t = lane & 3;

    smI[tid] = 1.0f / g_s[(size_t)bh * SEQ + qBase + tid];

    float* Ab = attn + ((size_t)bh * SEQ + qBase) * SEQ;
    const float* Vb = V + ((size_t)(b * SEQ)) * D_MODEL + h * DK;

    float acc[4][4][4] = {};
    float4 av[4], bvv;

    #pragma unroll
    for (int i = 0; i < 4; i++) {
        int e = tid + i * 256;
        av[i] = *(const float4*)(Ab + (size_t)(e >> 2) * SEQ + (e & 3) * 4);
    }
    bvv = *(const float4*)(Vb + (size_t)(tid >> 4) * D_MODEL + (tid & 15) * 4);
    __syncthreads();   // smI visible

    auto store_stage = [&](int buf, int kpos) {
        bf16* Ah = smb + buf * CT_STAGE;
        bf16* Al = Ah + 6144;
        bf16* Bh = Ah + 12288;
        bf16* Bl = Ah + 13440;
        #pragma unroll
        for (int i = 0; i < 4; i++) {
            int e = tid + i * 256;
            int m = e >> 2, k = (e & 3) * 4;
            float mI = smI[m];
            float4 p = make_float4(av[i].x * mI, av[i].y * mI,
                                   av[i].z * mI, av[i].w * mI);
            *(float4*)(Ab + (size_t)m * SEQ + kpos * 16 + k) = p;
            splitstore4(p, Ah + m * 24 + k, Al + m * 24 + k);
        }
        {
            int k = tid >> 4, n = (tid & 15) * 4;
            splitstore4(bvv, Bh + k * 72 + n, Bl + k * 72 + n);
        }
    };

    store_stage(0, 0);
    __syncthreads();

    const int NST = SEQ / 16;   // 128
    for (int s = 0; s < NST; s++) {
        int cur = s & 1;
        if (s + 1 < NST) {
            int k0 = (s + 1) * 16;
            #pragma unroll
            for (int i = 0; i < 4; i++) {
                int e = tid + i * 256;
                av[i] = *(const float4*)(Ab + (size_t)(e >> 2) * SEQ + k0 + (e & 3) * 4);
            }
            bvv = *(const float4*)(Vb + (size_t)(k0 + (tid >> 4)) * D_MODEL + (tid & 15) * 4);
        }
        bf16* base = smb + cur * CT_STAGE;
        warp_mma_k16<24, 72, true>(acc, base, base + 6144, base + 12288, base + 13440,
                                   warpM * 64, warpN * 32, 0, 0, lane);
        if (s + 1 < NST) store_stage(cur ^ 1, s + 1);
        __syncthreads();
    }

    #pragma unroll
    for (int mi = 0; mi < 4; mi++) {
        int q0 = qBase + warpM * 64 + mi * 16 + r;
        #pragma unroll
        for (int ni = 0; ni < 4; ni++) {
            int col = warpN * 32 + ni * 8 + t * 2;
            float2 v0 = {acc[mi][ni][0], acc[mi][ni][1]};
            float2 v1 = {acc[mi][ni][2], acc[mi][ni][3]};
            *(float2*)&ctx[((size_t)(b * SEQ + q0)) * D_MODEL + h * DK + col] = v0;
            *(float2*)&ctx[((size_t)(b * SEQ + q0 + 8)) * D_MODEL + h * DK + col] = v1;
        }
    }
}

// ---------------------------------------------------------------------------
extern "C" void kernel_launch(void* const* d_in, const int* in_sizes, int n_in,
                              void* d_out, int out_size)
{
    const float* query = (const float*)d_in[0];
    const float* key   = (const float*)d_in[1];
    const float* value = (const float*)d_in[2];
    const float* Wq = (const float*)d_in[3];
    const float* bq = (const float*)d_in[4];
    const float* Wk = (const float*)d_in[5];
    const float* bk = (const float*)d_in[6];
    const float* Wv = (const float*)d_in[7];
    const float* bv = (const float*)d_in[8];
    const float* Wo = (const float*)d_in[9];
    const float* bo = (const float*)d_in[10];

    float* out  = (float*)d_out;
    float* attn = (float*)d_out + OUT_ELEMS;

    float* Qp; cudaGetSymbolAddress((void**)&Qp, g_Q);
    float* Kp; cudaGetSymbolAddress((void**)&Kp, g_K);
    float* Vp; cudaGetSymbolAddress((void**)&Vp, g_V);
    float* Cp; cudaGetSymbolAddress((void**)&Cp, g_ctx);

    static int configured = 0;
    if (!configured) {
        cudaFuncSetAttribute(gemm_bias_tc, cudaFuncAttributeMaxDynamicSharedMemorySize,
                             PJ_SMEM_BYTES);
        cudaFuncSetAttribute(scores_tc, cudaFuncAttributeMaxDynamicSharedMemorySize,
                             SC_SMEM_BYTES);
        cudaFuncSetAttribute(ctx_tc, cudaFuncAttributeMaxDynamicSharedMemorySize,
                             CT_SMEM_BYTES);
        configured = 1;
    }

    dim3 gProj(D_MODEL / 128, MROWS / 128);   // (8, 32)
    dim3 gScores(SEQ / 128, NBH);             // (16, 32)
    dim3 gCtx(SEQ / 256, NBH);                // (8, 32)

    gemm_bias_tc<<<gProj, 256, PJ_SMEM_BYTES>>>(query, Wq, bq, Qp);
    gemm_bias_tc<<<gProj, 256, PJ_SMEM_BYTES>>>(key,   Wk, bk, Kp);
    gemm_bias_tc<<<gProj, 256, PJ_SMEM_BYTES>>>(value, Wv, bv, Vp);

    scores_tc<<<gScores, 256, SC_SMEM_BYTES>>>(Qp, Kp, attn);
    ctx_tc<<<gCtx, 256, CT_SMEM_BYTES>>>(attn, Vp, Cp);

    gemm_bias_tc<<<gProj, 256, PJ_SMEM_BYTES>>>(Cp, Wo, bo, out);
}

// round 8
// speedup vs baseline: 1.6490x; 1.0755x over previous
#include <cuda_runtime.h>
#include <cuda_bf16.h>
#include <math.h>

#define D_MODEL 1024
#define NHEAD   16
#define DK      64
#define BATCH   2
#define SEQ     2048
#define MROWS   (BATCH * SEQ)
#define NBH     (BATCH * NHEAD)
#define OUT_ELEMS ((size_t)MROWS * D_MODEL)

typedef __nv_bfloat16 bf16;

// Scratch (no cudaMalloc allowed)
__device__ float g_Q[MROWS * D_MODEL];
__device__ float g_K[MROWS * D_MODEL];
__device__ float g_V[MROWS * D_MODEL];
__device__ float g_ctx[MROWS * D_MODEL];

// ---------------------------------------------------------------------------
__device__ __forceinline__ unsigned smaddr(const void* p) {
    return (unsigned)__cvta_generic_to_shared(p);
}

__device__ __forceinline__ void splitstore4(float4 v, bf16* hb, bf16* lb) {
    float f[4] = {v.x, v.y, v.z, v.w};
    unsigned h[2], l[2];
    #pragma unroll
    for (int i = 0; i < 2; i++) {
        bf16 a = __float2bfloat16(f[2*i]);
        bf16 b = __float2bfloat16(f[2*i+1]);
        h[i] = ((unsigned)__bfloat16_as_ushort(b) << 16) | __bfloat16_as_ushort(a);
        bf16 ra = __float2bfloat16(f[2*i]   - __bfloat162float(a));
        bf16 rb = __float2bfloat16(f[2*i+1] - __bfloat162float(b));
        l[i] = ((unsigned)__bfloat16_as_ushort(rb) << 16) | __bfloat16_as_ushort(ra);
    }
    *(uint2*)hb = make_uint2(h[0], h[1]);
    *(uint2*)lb = make_uint2(l[0], l[1]);
}

// Split two adjacent fp32 into hi/lo bf16 pairs (one 4B store each).
__device__ __forceinline__ void split2(float a, float b, bf16* hp, bf16* lp) {
    bf16 ha = __float2bfloat16(a), hb = __float2bfloat16(b);
    unsigned hw = ((unsigned)__bfloat16_as_ushort(hb) << 16) | __bfloat16_as_ushort(ha);
    bf16 la = __float2bfloat16(a - __bfloat162float(ha));
    bf16 lb = __float2bfloat16(b - __bfloat162float(hb));
    unsigned lw = ((unsigned)__bfloat16_as_ushort(lb) << 16) | __bfloat16_as_ushort(la);
    *(unsigned*)hp = hw;
    *(unsigned*)lp = lw;
}

__device__ __forceinline__ void mma_bf16(float* c, const unsigned* a, const unsigned* b) {
    asm volatile(
        "mma.sync.aligned.m16n8k16.row.col.f32.bf16.bf16.f32 "
        "{%0,%1,%2,%3},{%4,%5,%6,%7},{%8,%9},{%0,%1,%2,%3};"
        : "+f"(c[0]), "+f"(c[1]), "+f"(c[2]), "+f"(c[3])
        : "r"(a[0]), "r"(a[1]), "r"(a[2]), "r"(a[3]), "r"(b[0]), "r"(b[1]));
}

__device__ __forceinline__ void ldsm4(unsigned& r0, unsigned& r1, unsigned& r2,
                                      unsigned& r3, unsigned a) {
    asm volatile("ldmatrix.sync.aligned.m8n8.x4.shared.b16 {%0,%1,%2,%3}, [%4];"
        : "=r"(r0), "=r"(r1), "=r"(r2), "=r"(r3) : "r"(a));
}
__device__ __forceinline__ void ldsm4t(unsigned& r0, unsigned& r1, unsigned& r2,
                                       unsigned& r3, unsigned a) {
    asm volatile("ldmatrix.sync.aligned.m8n8.x4.trans.shared.b16 {%0,%1,%2,%3}, [%4];"
        : "=r"(r0), "=r"(r1), "=r"(r2), "=r"(r3) : "r"(a));
}

// Warp tile 64(m) x (NJ*16)(n), one k16 slab, 3-term bf16.
// A: [m][k] rows (SA halves). B: BT=false -> [n][k] rows; BT=true -> [k][n] rows.
template<int SA, int SB, bool BT, int NJ>
__device__ __forceinline__ void warp_mma_k16(
    float (*acc)[NJ * 2][4],
    const bf16* Ah, const bf16* Al, const bf16* Bh, const bf16* Bl,
    int m0base, int n0base, int k0a, int k0b, int lane)
{
    int g = lane >> 3, r = lane & 7;
    unsigned ah[4][4], al[4][4], bh[NJ * 2][2], bl[NJ * 2][2];

    int arow = (g & 1) * 8 + r, acol = k0a + (g >> 1) * 8;
    #pragma unroll
    for (int mi = 0; mi < 4; mi++) {
        int row = m0base + mi * 16 + arow;
        ldsm4(ah[mi][0], ah[mi][1], ah[mi][2], ah[mi][3], smaddr(Ah + row * SA + acol));
        ldsm4(al[mi][0], al[mi][1], al[mi][2], al[mi][3], smaddr(Al + row * SA + acol));
    }
    #pragma unroll
    for (int nj = 0; nj < NJ; nj++) {
        int n0 = n0base + nj * 16;
        unsigned q0, q1, q2, q3;
        if (BT) {
            int row = k0b + (g & 1) * 8 + r;
            int col = n0 + (g >> 1) * 8;
            ldsm4t(q0, q1, q2, q3, smaddr(Bh + row * SB + col));
            bh[nj*2][0] = q0; bh[nj*2][1] = q1; bh[nj*2+1][0] = q2; bh[nj*2+1][1] = q3;
            ldsm4t(q0, q1, q2, q3, smaddr(Bl + row * SB + col));
            bl[nj*2][0] = q0; bl[nj*2][1] = q1; bl[nj*2+1][0] = q2; bl[nj*2+1][1] = q3;
        } else {
            int row = n0 + (g >> 1) * 8 + r;
            int col = k0b + (g & 1) * 8;
            ldsm4(q0, q1, q2, q3, smaddr(Bh + row * SB + col));
            bh[nj*2][0] = q0; bh[nj*2][1] = q1; bh[nj*2+1][0] = q2; bh[nj*2+1][1] = q3;
            ldsm4(q0, q1, q2, q3, smaddr(Bl + row * SB + col));
            bl[nj*2][0] = q0; bl[nj*2][1] = q1; bl[nj*2+1][0] = q2; bl[nj*2+1][1] = q3;
        }
    }
    #pragma unroll
    for (int mi = 0; mi < 4; mi++)
        #pragma unroll
        for (int ni = 0; ni < NJ * 2; ni++) {
            mma_bf16(acc[mi][ni], ah[mi], bh[ni]);
            mma_bf16(acc[mi][ni], ah[mi], bl[ni]);
            mma_bf16(acc[mi][ni], al[mi], bh[ni]);
        }
}

// ---------------------------------------------------------------------------
// Projection GEMM: Y = X @ W + b. BM=128, BN=128, BK=32, double-buffered.
// Stage (halves): Ah[128][40]=5120 | Al 5120 | Bh[32][136]=4352 | Bl 4352 = 18944.
// ---------------------------------------------------------------------------
#define PJ_STAGE 18944
#define PJ_SMEM_BYTES (2 * PJ_STAGE * 2)

__global__ __launch_bounds__(256) void gemm_bias_tc(
    const float* __restrict__ X, const float* __restrict__ W,
    const float* __restrict__ bias, float* __restrict__ Y)
{
    extern __shared__ bf16 smb[];

    int tid = threadIdx.x, lane = tid & 31, warp = tid >> 5;
    int warpM = warp >> 2, warpN = warp & 3;
    int rowBase = blockIdx.y * 128;
    int colBase = blockIdx.x * 128;

    const float* Xb = X + (size_t)rowBase * D_MODEL;
    const float* Wb = W + colBase;

    float acc[4][4][4] = {};
    float4 av[4], bv[4];

    #pragma unroll
    for (int i = 0; i < 4; i++) {
        int e = tid + i * 256;
        av[i] = *(const float4*)(Xb + (size_t)(e >> 3) * D_MODEL + (e & 7) * 4);
        bv[i] = *(const float4*)(Wb + (size_t)(e >> 5) * D_MODEL + (e & 31) * 4);
    }

    auto store_stage = [&](int buf) {
        bf16* Ah = smb + buf * PJ_STAGE;
        bf16* Al = Ah + 5120;
        bf16* Bh = Ah + 10240;
        bf16* Bl = Ah + 14592;
        #pragma unroll
        for (int i = 0; i < 4; i++) {
            int e = tid + i * 256;
            { int m = e >> 3, k = (e & 7) * 4;
              splitstore4(av[i], Ah + m * 40 + k, Al + m * 40 + k); }
            { int k = e >> 5, n = (e & 31) * 4;
              splitstore4(bv[i], Bh + k * 136 + n, Bl + k * 136 + n); }
        }
    };

    store_stage(0);
    __syncthreads();

    const int NST = D_MODEL / 32;   // 32
    for (int s = 0; s < NST; s++) {
        int cur = s & 1;
        if (s + 1 < NST) {
            const float* Xn = Xb + (s + 1) * 32;
            const float* Wn = Wb + (size_t)((s + 1) * 32) * D_MODEL;
            #pragma unroll
            for (int i = 0; i < 4; i++) {
                int e = tid + i * 256;
                av[i] = *(const float4*)(Xn + (size_t)(e >> 3) * D_MODEL + (e & 7) * 4);
                bv[i] = *(const float4*)(Wn + (size_t)(e >> 5) * D_MODEL + (e & 31) * 4);
            }
        }
        bf16* base = smb + cur * PJ_STAGE;
        warp_mma_k16<40, 136, true, 2>(acc, base, base + 5120, base + 10240, base + 14592,
                                       warpM * 64, warpN * 32, 0, 0, lane);
        warp_mma_k16<40, 136, true, 2>(acc, base, base + 5120, base + 10240, base + 14592,
                                       warpM * 64, warpN * 32, 16, 16, lane);
        if (s + 1 < NST) store_stage(cur ^ 1);
        __syncthreads();
    }

    int r = lane >> 2, t = lane & 3;
    #pragma unroll
    for (int mi = 0; mi < 4; mi++) {
        int row0 = rowBase + warpM * 64 + mi * 16 + r;
        #pragma unroll
        for (int ni = 0; ni < 4; ni++) {
            int col = colBase + warpN * 32 + ni * 8 + t * 2;
            float2 b2 = *(const float2*)&bias[col];
            float2 v0 = {acc[mi][ni][0] + b2.x, acc[mi][ni][1] + b2.y};
            float2 v1 = {acc[mi][ni][2] + b2.x, acc[mi][ni][3] + b2.y};
            *(float2*)&Y[(size_t)row0 * D_MODEL + col] = v0;
            *(float2*)&Y[(size_t)(row0 + 8) * D_MODEL + col] = v1;
        }
    }
}

// ---------------------------------------------------------------------------
// Fused attention: per CTA (q-tile 128, bh):
//   for each s-tile (16): S = Q K^T (3-term), e = exp(S/8) -> gmem + smem(P),
//   V tile co-staged, ctx_acc += P @ V (3-term).
//   End: row sums -> smI = 1/s; ctx written scaled; attn region rescaled
//   in place (own writes, L2-hot, __ldcg).
// smem (bf16 halves): Qh 0 | Ql 9216 | K 18432 (2 stages x 6144) |
//   Ph 30720 | Pl 48128 | Vh 65536 | Vl 74752 | end 83968
// floats after byte 167936: RedS[4][128], smI[128]
// ---------------------------------------------------------------------------
#define AT_KB   18432
#define AT_PH   30720
#define AT_PL   48128
#define AT_VH   65536
#define AT_VL   74752
#define AT_RS_BYTE 167936
#define AT_SMI_BYTE (AT_RS_BYTE + 2048)
#define AT_SMEM_BYTES (AT_SMI_BYTE + 512)

__global__ __launch_bounds__(256) void attn_fused(
    const float* __restrict__ Q, const float* __restrict__ Kmat,
    const float* __restrict__ V,
    float* __restrict__ attn, float* __restrict__ ctx)
{
    extern __shared__ bf16 smb[];
    bf16* Qh = smb;
    bf16* Ql = smb + 9216;
    bf16* Ph = smb + AT_PH;
    bf16* Pl = smb + AT_PL;
    bf16* Vh = smb + AT_VH;
    bf16* Vl = smb + AT_VL;
    float (*RedS)[128] = (float(*)[128])((char*)smb + AT_RS_BYTE);
    float* smI = (float*)((char*)smb + AT_SMI_BYTE);

    int tid = threadIdx.x, lane = tid & 31, warp = tid >> 5;
    int warpM = warp >> 2, warpN = warp & 3;
    int qBase = blockIdx.x * 128;
    int bh = blockIdx.y, b = bh >> 4, h = bh & 15;
    int r = lane >> 2, t = lane & 3;

    const float* Qb  = Q    + ((size_t)(b * SEQ + qBase)) * D_MODEL + h * DK;
    const float* Kb0 = Kmat + ((size_t)(b * SEQ))         * D_MODEL + h * DK;
    const float* Vb0 = V    + ((size_t)(b * SEQ))         * D_MODEL + h * DK;

    // Hoist full 128x64 Q tile.
    #pragma unroll
    for (int i = 0; i < 8; i++) {
        int e = tid + i * 256;
        int m = e >> 4, k = (e & 15) * 4;
        float4 v = *(const float4*)(Qb + (size_t)m * D_MODEL + k);
        splitstore4(v, Qh + m * 72 + k, Ql + m * 72 + k);
    }

    float4 bv[2], vv[2];
    #pragma unroll
    for (int i = 0; i < 2; i++) {
        int e = tid + i * 256;
        bv[i] = *(const float4*)(Kb0 + (size_t)(e >> 2) * D_MODEL + (e & 3) * 4);
    }

    auto kstore = [&](int buf) {
        bf16* Kh = smb + AT_KB + buf * 6144;
        bf16* Kl = Kh + 3072;
        #pragma unroll
        for (int i = 0; i < 2; i++) {
            int e = tid + i * 256;
            int n = e >> 2, k = (e & 3) * 4;
            splitstore4(bv[i], Kh + n * 24 + k, Kl + n * 24 + k);
        }
    };

    kstore(0);
    __syncthreads();

    float rs[8];
    #pragma unroll
    for (int j = 0; j < 8; j++) rs[j] = 0.0f;
    float cacc[4][2][4] = {};

    const float scale = 0.125f;
    const int NSTAGE = 64;

    for (int st = 0; st < 16; st++) {
        int sBase = st * 128;
        float acc[4][4][4] = {};

        #pragma unroll
        for (int kk = 0; kk < 4; kk++) {
            int stage = st * 4 + kk;
            int cur = stage & 1;
            // load V chunk (st, kk)
            {
                const float* Vc = Vb0 + (size_t)sBase * D_MODEL + kk * 16;
                #pragma unroll
                for (int i = 0; i < 2; i++) {
                    int e = tid + i * 256;
                    vv[i] = *(const float4*)(Vc + (size_t)(e >> 2) * D_MODEL + (e & 3) * 4);
                }
            }
            // prefetch next K chunk
            if (stage + 1 < NSTAGE) {
                int nst = (stage + 1) >> 2, nkk = (stage + 1) & 3;
                const float* Kb = Kb0 + (size_t)(nst * 128) * D_MODEL + nkk * 16;
                #pragma unroll
                for (int i = 0; i < 2; i++) {
                    int e = tid + i * 256;
                    bv[i] = *(const float4*)(Kb + (size_t)(e >> 2) * D_MODEL + (e & 3) * 4);
                }
            }
            bf16* Kh = smb + AT_KB + cur * 6144;
            warp_mma_k16<72, 24, false, 2>(acc, Qh, Ql, Kh, Kh + 3072,
                                           warpM * 64, warpN * 32, kk * 16, 0, lane);
            // store V chunk (current tile), K chunk (next stage)
            #pragma unroll
            for (int i = 0; i < 2; i++) {
                int e = tid + i * 256;
                int s2 = e >> 2, k = (e & 3) * 4;
                splitstore4(vv[i], Vh + s2 * 72 + kk * 16 + k, Vl + s2 * 72 + kk * 16 + k);
            }
            if (stage + 1 < NSTAGE) kstore(cur ^ 1);
            __syncthreads();
        }

        // Epilogue: e = exp(score), write gmem + P smem, accumulate row sums.
        #pragma unroll
        for (int mi = 0; mi < 4; mi++) {
            #pragma unroll
            for (int hh = 0; hh < 2; hh++) {
                int rowL = warpM * 64 + mi * 16 + hh * 8 + r;
                size_t rowOff = ((size_t)bh * SEQ + qBase + rowL) * SEQ;
                int j = mi * 2 + hh;
                float add = 0.0f;
                #pragma unroll
                for (int ni = 0; ni < 4; ni++) {
                    float e0 = __expf(acc[mi][ni][hh * 2 + 0] * scale);
                    float e1 = __expf(acc[mi][ni][hh * 2 + 1] * scale);
                    int col = warpN * 32 + ni * 8 + t * 2;
                    *(float2*)&attn[rowOff + sBase + col] = make_float2(e0, e1);
                    split2(e0, e1, Ph + rowL * 136 + col, Pl + rowL * 136 + col);
                    add += e0 + e1;
                }
                rs[j] += add;
            }
        }
        __syncthreads();   // P, V visible

        // ctx_acc += P @ V  (128x128 @ 128x64), warp tile 64q x 16d
        #pragma unroll
        for (int k0 = 0; k0 < 128; k0 += 16)
            warp_mma_k16<136, 72, true, 1>(cacc, Ph, Pl, Vh, Vl,
                                           warpM * 64, warpN * 16, k0, k0, lane);
        __syncthreads();   // P, V reusable
    }

    // Reduce row sums across t-lanes, then across warpN columns.
    #pragma unroll
    for (int off = 1; off <= 2; off <<= 1)
        #pragma unroll
        for (int j = 0; j < 8; j++)
            rs[j] += __shfl_xor_sync(0xFFFFFFFFu, rs[j], off);
    if (t == 0) {
        #pragma unroll
        for (int mi = 0; mi < 4; mi++)
            #pragma unroll
            for (int hh = 0; hh < 2; hh++) {
                int row = warpM * 64 + mi * 16 + hh * 8 + r;
                RedS[warpN][row] = rs[mi * 2 + hh];
            }
    }
    __syncthreads();
    if (tid < 128) {
        float s = RedS[0][tid] + RedS[1][tid] + RedS[2][tid] + RedS[3][tid];
        smI[tid] = 1.0f / s;
    }
    __syncthreads();

    // Write ctx scaled by 1/s.
    #pragma unroll
    for (int mi = 0; mi < 4; mi++) {
        int rowL0 = warpM * 64 + mi * 16 + r;
        float i0 = smI[rowL0], i1 = smI[rowL0 + 8];
        #pragma unroll
        for (int ni = 0; ni < 2; ni++) {
            int col = h * DK + warpN * 16 + ni * 8 + t * 2;
            float2 v0 = {cacc[mi][ni][0] * i0, cacc[mi][ni][1] * i0};
            float2 v1 = {cacc[mi][ni][2] * i1, cacc[mi][ni][3] * i1};
            *(float2*)&ctx[((size_t)(b * SEQ + qBase + rowL0)) * D_MODEL + col] = v0;
            *(float2*)&ctx[((size_t)(b * SEQ + qBase + rowL0 + 8)) * D_MODEL + col] = v1;
        }
    }

    // Rescale this CTA's attn region in place: p = e * (1/s).
    float* Abase = attn + ((size_t)bh * SEQ + qBase) * SEQ;
    for (int it = 0; it < 256; it++) {
        int idx = tid + it * 256;          // 0..65535
        int row = idx >> 9;                // 512 float4 per row
        int c4 = (idx & 511) * 4;
        float4 v = __ldcg((const float4*)(Abase + (size_t)row * SEQ + c4));
        float inv = smI[row];
        v.x *= inv; v.y *= inv; v.z *= inv; v.w *= inv;
        *(float4*)(Abase + (size_t)row * SEQ + c4) = v;
    }
}

// ---------------------------------------------------------------------------
extern "C" void kernel_launch(void* const* d_in, const int* in_sizes, int n_in,
                              void* d_out, int out_size)
{
    const float* query = (const float*)d_in[0];
    const float* key   = (const float*)d_in[1];
    const float* value = (const float*)d_in[2];
    const float* Wq = (const float*)d_in[3];
    const float* bq = (const float*)d_in[4];
    const float* Wk = (const float*)d_in[5];
    const float* bk = (const float*)d_in[6];
    const float* Wv = (const float*)d_in[7];
    const float* bv = (const float*)d_in[8];
    const float* Wo = (const float*)d_in[9];
    const float* bo = (const float*)d_in[10];

    float* out  = (float*)d_out;
    float* attn = (float*)d_out + OUT_ELEMS;

    float* Qp; cudaGetSymbolAddress((void**)&Qp, g_Q);
    float* Kp; cudaGetSymbolAddress((void**)&Kp, g_K);
    float* Vp; cudaGetSymbolAddress((void**)&Vp, g_V);
    float* Cp; cudaGetSymbolAddress((void**)&Cp, g_ctx);

    static int configured = 0;
    if (!configured) {
        cudaFuncSetAttribute(gemm_bias_tc, cudaFuncAttributeMaxDynamicSharedMemorySize,
                             PJ_SMEM_BYTES);
        cudaFuncSetAttribute(attn_fused, cudaFuncAttributeMaxDynamicSharedMemorySize,
                             AT_SMEM_BYTES);
        configured = 1;
    }

    dim3 gProj(D_MODEL / 128, MROWS / 128);   // (8, 32)
    dim3 gAttn(SEQ / 128, NBH);               // (16, 32)

    gemm_bias_tc<<<gProj, 256, PJ_SMEM_BYTES>>>(query, Wq, bq, Qp);
    gemm_bias_tc<<<gProj, 256, PJ_SMEM_BYTES>>>(key,   Wk, bk, Kp);
    gemm_bias_tc<<<gProj, 256, PJ_SMEM_BYTES>>>(value, Wv, bv, Vp);

    attn_fused<<<gAttn, 256, AT_SMEM_BYTES>>>(Qp, Kp, Vp, attn, Cp);

    gemm_bias_tc<<<gProj, 256, PJ_SMEM_BYTES>>>(Cp, Wo, bo, out);
}

// round 9
// speedup vs baseline: 1.8797x; 1.1399x over previous
#include <cuda_runtime.h>
#include <cuda_bf16.h>
#include <math.h>

#define D_MODEL 1024
#define NHEAD   16
#define DK      64
#define BATCH   2
#define SEQ     2048
#define MROWS   (BATCH * SEQ)
#define NBH     (BATCH * NHEAD)
#define OUT_ELEMS ((size_t)MROWS * D_MODEL)

typedef __nv_bfloat16 bf16;

// Scratch (no cudaMalloc allowed)
__device__ float g_Q[MROWS * D_MODEL];
__device__ float g_K[MROWS * D_MODEL];
__device__ float g_V[MROWS * D_MODEL];
__device__ float g_ctx[MROWS * D_MODEL];
__device__ float g_s[NBH * SEQ];

// ---------------------------------------------------------------------------
__device__ __forceinline__ unsigned smaddr(const void* p) {
    return (unsigned)__cvta_generic_to_shared(p);
}

__device__ __forceinline__ void splitstore4(float4 v, bf16* hb, bf16* lb) {
    float f[4] = {v.x, v.y, v.z, v.w};
    unsigned h[2], l[2];
    #pragma unroll
    for (int i = 0; i < 2; i++) {
        bf16 a = __float2bfloat16(f[2*i]);
        bf16 b = __float2bfloat16(f[2*i+1]);
        h[i] = ((unsigned)__bfloat16_as_ushort(b) << 16) | __bfloat16_as_ushort(a);
        bf16 ra = __float2bfloat16(f[2*i]   - __bfloat162float(a));
        bf16 rb = __float2bfloat16(f[2*i+1] - __bfloat162float(b));
        l[i] = ((unsigned)__bfloat16_as_ushort(rb) << 16) | __bfloat16_as_ushort(ra);
    }
    *(uint2*)hb = make_uint2(h[0], h[1]);
    *(uint2*)lb = make_uint2(l[0], l[1]);
}

__device__ __forceinline__ void mma_bf16(float* c, const unsigned* a, const unsigned* b) {
    asm volatile(
        "mma.sync.aligned.m16n8k16.row.col.f32.bf16.bf16.f32 "
        "{%0,%1,%2,%3},{%4,%5,%6,%7},{%8,%9},{%0,%1,%2,%3};"
        : "+f"(c[0]), "+f"(c[1]), "+f"(c[2]), "+f"(c[3])
        : "r"(a[0]), "r"(a[1]), "r"(a[2]), "r"(a[3]), "r"(b[0]), "r"(b[1]));
}

__device__ __forceinline__ void ldsm4(unsigned& r0, unsigned& r1, unsigned& r2,
                                      unsigned& r3, unsigned a) {
    asm volatile("ldmatrix.sync.aligned.m8n8.x4.shared.b16 {%0,%1,%2,%3}, [%4];"
        : "=r"(r0), "=r"(r1), "=r"(r2), "=r"(r3) : "r"(a));
}
__device__ __forceinline__ void ldsm4t(unsigned& r0, unsigned& r1, unsigned& r2,
                                       unsigned& r3, unsigned a) {
    asm volatile("ldmatrix.sync.aligned.m8n8.x4.trans.shared.b16 {%0,%1,%2,%3}, [%4];"
        : "=r"(r0), "=r"(r1), "=r"(r2), "=r"(r3) : "r"(a));
}

// Warp tile 64(m) x (NJ*16)(n), one k16 slab, 3-term bf16.
// A: [m][k] rows (SA halves). B: BT=false -> [n][k] rows; BT=true -> [k][n] rows.
template<int SA, int SB, bool BT, int NJ>
__device__ __forceinline__ void warp_mma_k16(
    float (*acc)[NJ * 2][4],
    const bf16* Ah, const bf16* Al, const bf16* Bh, const bf16* Bl,
    int m0base, int n0base, int k0a, int k0b, int lane)
{
    int g = lane >> 3, r = lane & 7;
    unsigned ah[4][4], al[4][4], bh[NJ * 2][2], bl[NJ * 2][2];

    int arow = (g & 1) * 8 + r, acol = k0a + (g >> 1) * 8;
    #pragma unroll
    for (int mi = 0; mi < 4; mi++) {
        int row = m0base + mi * 16 + arow;
        ldsm4(ah[mi][0], ah[mi][1], ah[mi][2], ah[mi][3], smaddr(Ah + row * SA + acol));
        ldsm4(al[mi][0], al[mi][1], al[mi][2], al[mi][3], smaddr(Al + row * SA + acol));
    }
    #pragma unroll
    for (int nj = 0; nj < NJ; nj++) {
        int n0 = n0base + nj * 16;
        unsigned q0, q1, q2, q3;
        if (BT) {
            int row = k0b + (g & 1) * 8 + r;
            int col = n0 + (g >> 1) * 8;
            ldsm4t(q0, q1, q2, q3, smaddr(Bh + row * SB + col));
            bh[nj*2][0] = q0; bh[nj*2][1] = q1; bh[nj*2+1][0] = q2; bh[nj*2+1][1] = q3;
            ldsm4t(q0, q1, q2, q3, smaddr(Bl + row * SB + col));
            bl[nj*2][0] = q0; bl[nj*2][1] = q1; bl[nj*2+1][0] = q2; bl[nj*2+1][1] = q3;
        } else {
            int row = n0 + (g >> 1) * 8 + r;
            int col = k0b + (g & 1) * 8;
            ldsm4(q0, q1, q2, q3, smaddr(Bh + row * SB + col));
            bh[nj*2][0] = q0; bh[nj*2][1] = q1; bh[nj*2+1][0] = q2; bh[nj*2+1][1] = q3;
            ldsm4(q0, q1, q2, q3, smaddr(Bl + row * SB + col));
            bl[nj*2][0] = q0; bl[nj*2][1] = q1; bl[nj*2+1][0] = q2; bl[nj*2+1][1] = q3;
        }
    }
    #pragma unroll
    for (int mi = 0; mi < 4; mi++)
        #pragma unroll
        for (int ni = 0; ni < NJ * 2; ni++) {
            mma_bf16(acc[mi][ni], ah[mi], bh[ni]);
            mma_bf16(acc[mi][ni], ah[mi], bl[ni]);
            mma_bf16(acc[mi][ni], al[mi], bh[ni]);
        }
}

// ---------------------------------------------------------------------------
// Projection GEMM: Y = X @ W + b. BM=128, BN=128, BK=32, double-buffered.
// Stage (halves): Ah[128][40]=5120 | Al 5120 | Bh[32][136]=4352 | Bl 4352 = 18944.
// ---------------------------------------------------------------------------
#define PJ_STAGE 18944
#define PJ_SMEM_BYTES (2 * PJ_STAGE * 2)

__global__ __launch_bounds__(256) void gemm_bias_tc(
    const float* __restrict__ X, const float* __restrict__ W,
    const float* __restrict__ bias, float* __restrict__ Y)
{
    extern __shared__ bf16 smb[];

    int tid = threadIdx.x, lane = tid & 31, warp = tid >> 5;
    int warpM = warp >> 2, warpN = warp & 3;
    int rowBase = blockIdx.y * 128;
    int colBase = blockIdx.x * 128;

    const float* Xb = X + (size_t)rowBase * D_MODEL;
    const float* Wb = W + colBase;

    float acc[4][4][4] = {};
    float4 av[4], bv[4];

    #pragma unroll
    for (int i = 0; i < 4; i++) {
        int e = tid + i * 256;
        av[i] = *(const float4*)(Xb + (size_t)(e >> 3) * D_MODEL + (e & 7) * 4);
        bv[i] = *(const float4*)(Wb + (size_t)(e >> 5) * D_MODEL + (e & 31) * 4);
    }

    auto store_stage = [&](int buf) {
        bf16* Ah = smb + buf * PJ_STAGE;
        bf16* Al = Ah + 5120;
        bf16* Bh = Ah + 10240;
        bf16* Bl = Ah + 14592;
        #pragma unroll
        for (int i = 0; i < 4; i++) {
            int e = tid + i * 256;
            { int m = e >> 3, k = (e & 7) * 4;
              splitstore4(av[i], Ah + m * 40 + k, Al + m * 40 + k); }
            { int k = e >> 5, n = (e & 31) * 4;
              splitstore4(bv[i], Bh + k * 136 + n, Bl + k * 136 + n); }
        }
    };

    store_stage(0);
    __syncthreads();

    const int NST = D_MODEL / 32;   // 32
    for (int s = 0; s < NST; s++) {
        int cur = s & 1;
        if (s + 1 < NST) {
            const float* Xn = Xb + (s + 1) * 32;
            const float* Wn = Wb + (size_t)((s + 1) * 32) * D_MODEL;
            #pragma unroll
            for (int i = 0; i < 4; i++) {
                int e = tid + i * 256;
                av[i] = *(const float4*)(Xn + (size_t)(e >> 3) * D_MODEL + (e & 7) * 4);
                bv[i] = *(const float4*)(Wn + (size_t)(e >> 5) * D_MODEL + (e & 31) * 4);
            }
        }
        bf16* base = smb + cur * PJ_STAGE;
        warp_mma_k16<40, 136, true, 2>(acc, base, base + 5120, base + 10240, base + 14592,
                                       warpM * 64, warpN * 32, 0, 0, lane);
        warp_mma_k16<40, 136, true, 2>(acc, base, base + 5120, base + 10240, base + 14592,
                                       warpM * 64, warpN * 32, 16, 16, lane);
        if (s + 1 < NST) store_stage(cur ^ 1);
        __syncthreads();
    }

    int r = lane >> 2, t = lane & 3;
    #pragma unroll
    for (int mi = 0; mi < 4; mi++) {
        int row0 = rowBase + warpM * 64 + mi * 16 + r;
        #pragma unroll
        for (int ni = 0; ni < 4; ni++) {
            int col = colBase + warpN * 32 + ni * 8 + t * 2;
            float2 b2 = *(const float2*)&bias[col];
            float2 v0 = {acc[mi][ni][0] + b2.x, acc[mi][ni][1] + b2.y};
            float2 v1 = {acc[mi][ni][2] + b2.x, acc[mi][ni][3] + b2.y};
            *(float2*)&Y[(size_t)row0 * D_MODEL + col] = v0;
            *(float2*)&Y[(size_t)(row0 + 8) * D_MODEL + col] = v1;
        }
    }
}

// ---------------------------------------------------------------------------
// scores: e = exp(score) + row sums. Q tile hoisted; K staged as FULL 128x64
// tiles, double-buffered -> ONE barrier per s-tile (16 total).
// Halves: Qh 0 | Ql 9216 | K buffers at 18432 (2 x 18432: Kh 9216 + Kl 9216).
// RedS floats at byte 110592.
// ---------------------------------------------------------------------------
#define SC_KB 18432
#define SC_RS_BYTE 110592
#define SC_SMEM_BYTES (SC_RS_BYTE + 2048)

__global__ __launch_bounds__(256) void scores_tc(
    const float* __restrict__ Q, const float* __restrict__ Kmat,
    float* __restrict__ attn)
{
    extern __shared__ bf16 smb[];
    bf16* Qh = smb;
    bf16* Ql = smb + 9216;
    float (*RedS)[128] = (float(*)[128])((char*)smb + SC_RS_BYTE);

    int tid = threadIdx.x, lane = tid & 31, warp = tid >> 5;
    int warpM = warp >> 2, warpN = warp & 3;
    int qBase = blockIdx.x * 128;
    int bh = blockIdx.y, b = bh >> 4, h = bh & 15;
    int r = lane >> 2, t = lane & 3;

    const float* Qb  = Q    + ((size_t)(b * SEQ + qBase)) * D_MODEL + h * DK;
    const float* Kb0 = Kmat + ((size_t)(b * SEQ))         * D_MODEL + h * DK;

    // Hoist full 128x64 Q tile.
    #pragma unroll
    for (int i = 0; i < 8; i++) {
        int e = tid + i * 256;
        int m = e >> 4, k = (e & 15) * 4;
        float4 v = *(const float4*)(Qb + (size_t)m * D_MODEL + k);
        splitstore4(v, Qh + m * 72 + k, Ql + m * 72 + k);
    }

    float4 kv[8];
    auto kload = [&](int st) {
        const float* Kb = Kb0 + (size_t)(st * 128) * D_MODEL;
        #pragma unroll
        for (int i = 0; i < 8; i++) {
            int e = tid + i * 256;
            kv[i] = *(const float4*)(Kb + (size_t)(e >> 4) * D_MODEL + (e & 15) * 4);
        }
    };
    auto kstore = [&](int buf) {
        bf16* Kh = smb + SC_KB + buf * 18432;
        bf16* Kl = Kh + 9216;
        #pragma unroll
        for (int i = 0; i < 8; i++) {
            int e = tid + i * 256;
            int m = e >> 4, k = (e & 15) * 4;
            splitstore4(kv[i], Kh + m * 72 + k, Kl + m * 72 + k);
        }
    };

    kload(0);
    kstore(0);
    __syncthreads();

    float rs[8];
    #pragma unroll
    for (int j = 0; j < 8; j++) rs[j] = 0.0f;

    const float scale = 0.125f;

    for (int st = 0; st < 16; st++) {
        int cur = st & 1;
        if (st + 1 < 16) kload(st + 1);

        float acc[4][4][4] = {};
        bf16* Kh = smb + SC_KB + cur * 18432;
        bf16* Kl = Kh + 9216;
        #pragma unroll
        for (int kk = 0; kk < 4; kk++)
            warp_mma_k16<72, 72, false, 2>(acc, Qh, Ql, Kh, Kl,
                                           warpM * 64, warpN * 32, kk * 16, kk * 16, lane);

        if (st + 1 < 16) kstore(cur ^ 1);
        __syncthreads();

        // Epilogue: e = exp(score), write, accumulate row sums.
        int sBase = st * 128;
        #pragma unroll
        for (int mi = 0; mi < 4; mi++) {
            #pragma unroll
            for (int hh = 0; hh < 2; hh++) {
                int row = qBase + warpM * 64 + mi * 16 + hh * 8 + r;
                size_t rowOff = ((size_t)bh * SEQ + row) * SEQ;
                int j = mi * 2 + hh;
                float add = 0.0f;
                #pragma unroll
                for (int ni = 0; ni < 4; ni++) {
                    float e0 = __expf(acc[mi][ni][hh * 2 + 0] * scale);
                    float e1 = __expf(acc[mi][ni][hh * 2 + 1] * scale);
                    int col = sBase + warpN * 32 + ni * 8 + t * 2;
                    *(float2*)&attn[rowOff + col] = make_float2(e0, e1);
                    add += e0 + e1;
                }
                rs[j] += add;
            }
        }
    }

    #pragma unroll
    for (int off = 1; off <= 2; off <<= 1)
        #pragma unroll
        for (int j = 0; j < 8; j++)
            rs[j] += __shfl_xor_sync(0xFFFFFFFFu, rs[j], off);
    if (t == 0) {
        #pragma unroll
        for (int mi = 0; mi < 4; mi++)
            #pragma unroll
            for (int hh = 0; hh < 2; hh++) {
                int row = warpM * 64 + mi * 16 + hh * 8 + r;
                RedS[warpN][row] = rs[mi * 2 + hh];
            }
    }
    __syncthreads();
    if (tid < 128) {
        float s = RedS[0][tid] + RedS[1][tid] + RedS[2][tid] + RedS[3][tid];
        g_s[(size_t)bh * SEQ + qBase + tid] = s;
    }
}

// ---------------------------------------------------------------------------
// ctx: p = e / s (writes normalized attn), ctx = P @ V.
// BM=256(q), BN=64(dk), BK=32(s), double-buffered, one barrier per stage (64).
// Stage halves: Ah[256][40]=10240 | Al 10240 | Bh[32][72]=2304 | Bl 2304 = 25088.
// smI floats at byte 100352.
// ---------------------------------------------------------------------------
#define CT_STAGE 25088
#define CT_SMI_BYTE 100352
#define CT_SMEM_BYTES (CT_SMI_BYTE + 1024)

__global__ __launch_bounds__(256) void ctx_tc(
    float* __restrict__ attn, const float* __restrict__ V,
    float* __restrict__ ctx)
{
    extern __shared__ bf16 smb[];
    float* smI = (float*)((char*)smb + CT_SMI_BYTE);

    int tid = threadIdx.x, lane = tid & 31, warp = tid >> 5;
    int warpM = warp >> 1, warpN = warp & 1;
    int qBase = blockIdx.x * 256;
    int bh = blockIdx.y, b = bh >> 4, h = bh & 15;
    int r = lane >> 2, t = lane & 3;

    smI[tid] = 1.0f / g_s[(size_t)bh * SEQ + qBase + tid];

    float* Ab = attn + ((size_t)bh * SEQ + qBase) * SEQ;
    const float* Vb = V + ((size_t)(b * SEQ)) * D_MODEL + h * DK;

    float acc[4][4][4] = {};
    float4 av[8], bv2[2];

    auto aload = [&](int kpos) {   // A: 256 rows x 32 cols from column kpos*32
        #pragma unroll
        for (int i = 0; i < 8; i++) {
            int e = tid + i * 256;
            av[i] = *(const float4*)(Ab + (size_t)(e >> 3) * SEQ + kpos * 32 + (e & 7) * 4);
        }
    };
    auto bload = [&](int kpos) {   // V: 32 rows x 64 cols from row kpos*32
        #pragma unroll
        for (int i = 0; i < 2; i++) {
            int e = tid + i * 256;
            bv2[i] = *(const float4*)(Vb + (size_t)(kpos * 32 + (e >> 4)) * D_MODEL + (e & 15) * 4);
        }
    };

    aload(0);
    bload(0);
    __syncthreads();   // smI visible

    auto store_stage = [&](int buf, int kpos) {
        bf16* Ah = smb + buf * CT_STAGE;
        bf16* Al = Ah + 10240;
        bf16* Bh = Ah + 20480;
        bf16* Bl = Ah + 22784;
        #pragma unroll
        for (int i = 0; i < 8; i++) {
            int e = tid + i * 256;
            int m = e >> 3, k = (e & 7) * 4;
            float mI = smI[m];
            float4 p = make_float4(av[i].x * mI, av[i].y * mI,
                                   av[i].z * mI, av[i].w * mI);
            *(float4*)(Ab + (size_t)m * SEQ + kpos * 32 + k) = p;
            splitstore4(p, Ah + m * 40 + k, Al + m * 40 + k);
        }
        #pragma unroll
        for (int i = 0; i < 2; i++) {
            int e = tid + i * 256;
            int krow = e >> 4, n = (e & 15) * 4;
            splitstore4(bv2[i], Bh + krow * 72 + n, Bl + krow * 72 + n);
        }
    };

    store_stage(0, 0);
    __syncthreads();

    const int NST = SEQ / 32;   // 64
    for (int s = 0; s < NST; s++) {
        int cur = s & 1;
        if (s + 1 < NST) { aload(s + 1); bload(s + 1); }

        bf16* base = smb + cur * CT_STAGE;
        warp_mma_k16<40, 72, true, 2>(acc, base, base + 10240, base + 20480, base + 22784,
                                      warpM * 64, warpN * 32, 0, 0, lane);
        warp_mma_k16<40, 72, true, 2>(acc, base, base + 10240, base + 20480, base + 22784,
                                      warpM * 64, warpN * 32, 16, 16, lane);

        if (s + 1 < NST) store_stage(cur ^ 1, s + 1);
        __syncthreads();
    }

    #pragma unroll
    for (int mi = 0; mi < 4; mi++) {
        int q0 = qBase + warpM * 64 + mi * 16 + r;
        #pragma unroll
        for (int ni = 0; ni < 4; ni++) {
            int col = warpN * 32 + ni * 8 + t * 2;
            float2 v0 = {acc[mi][ni][0], acc[mi][ni][1]};
            float2 v1 = {acc[mi][ni][2], acc[mi][ni][3]};
            *(float2*)&ctx[((size_t)(b * SEQ + q0)) * D_MODEL + h * DK + col] = v0;
            *(float2*)&ctx[((size_t)(b * SEQ + q0 + 8)) * D_MODEL + h * DK + col] = v1;
        }
    }
}

// ---------------------------------------------------------------------------
extern "C" void kernel_launch(void* const* d_in, const int* in_sizes, int n_in,
                              void* d_out, int out_size)
{
    const float* query = (const float*)d_in[0];
    const float* key   = (const float*)d_in[1];
    const float* value = (const float*)d_in[2];
    const float* Wq = (const float*)d_in[3];
    const float* bq = (const float*)d_in[4];
    const float* Wk = (const float*)d_in[5];
    const float* bk = (const float*)d_in[6];
    const float* Wv = (const float*)d_in[7];
    const float* bv = (const float*)d_in[8];
    const float* Wo = (const float*)d_in[9];
    const float* bo = (const float*)d_in[10];

    float* out  = (float*)d_out;
    float* attn = (float*)d_out + OUT_ELEMS;

    float* Qp; cudaGetSymbolAddress((void**)&Qp, g_Q);
    float* Kp; cudaGetSymbolAddress((void**)&Kp, g_K);
    float* Vp; cudaGetSymbolAddress((void**)&Vp, g_V);
    float* Cp; cudaGetSymbolAddress((void**)&Cp, g_ctx);

    static int configured = 0;
    if (!configured) {
        cudaFuncSetAttribute(gemm_bias_tc, cudaFuncAttributeMaxDynamicSharedMemorySize,
                             PJ_SMEM_BYTES);
        cudaFuncSetAttribute(scores_tc, cudaFuncAttributeMaxDynamicSharedMemorySize,
                             SC_SMEM_BYTES);
        cudaFuncSetAttribute(ctx_tc, cudaFuncAttributeMaxDynamicSharedMemorySize,
                             CT_SMEM_BYTES);
        configured = 1;
    }

    dim3 gProj(D_MODEL / 128, MROWS / 128);   // (8, 32)
    dim3 gScores(SEQ / 128, NBH);             // (16, 32)
    dim3 gCtx(SEQ / 256, NBH);                // (8, 32)

    gemm_bias_tc<<<gProj, 256, PJ_SMEM_BYTES>>>(query, Wq, bq, Qp);
    gemm_bias_tc<<<gProj, 256, PJ_SMEM_BYTES>>>(key,   Wk, bk, Kp);
    gemm_bias_tc<<<gProj, 256, PJ_SMEM_BYTES>>>(value, Wv, bv, Vp);

    scores_tc<<<gScores, 256, SC_SMEM_BYTES>>>(Qp, Kp, attn);
    ctx_tc<<<gCtx, 256, CT_SMEM_BYTES>>>(attn, Vp, Cp);

    gemm_bias_tc<<<gProj, 256, PJ_SMEM_BYTES>>>(Cp, Wo, bo, out);
}